// round 3
// baseline (speedup 1.0000x reference)
#include <cuda_runtime.h>
#include <cstddef>
#include <cstdint>

// CubePadding: x [6,128,512,512] f32, pad=1 -> out [6,128,514,514] f32.
// Faces order: 0=back, 1=down, 2=front, 3=left, 4=right, 5=top.

#define C_   128
#define H_   512
#define W_   512
#define OH_  514
#define OW_  514

__device__ __forceinline__ const float* facePlane(const float* chanBase, int face) {
    // chanBase = in + c*H*W ; plane(face) = in + (face*C + c)*H*W
    return chanBase + (size_t)face * ((size_t)C_ * H_ * W_);
}

// ---- border gathers (p = 1) ----  h, w in [0, 511].

__device__ __forceinline__ float load_top(const float* cb, int f, int w) {
    switch (f) {
        case 0: return __ldg(facePlane(cb, 5) + (511 - w));                    // top[0, 511-w]
        case 1: return __ldg(facePlane(cb, 2) + (size_t)511 * W_ + w);         // front[511, w]
        case 2: return __ldg(facePlane(cb, 5) + (size_t)511 * W_ + w);         // top[511, w]
        case 3: return __ldg(facePlane(cb, 5) + (size_t)w * W_);               // top[w, 0]
        case 4: return __ldg(facePlane(cb, 5) + (size_t)(511 - w) * W_ + 511); // top[511-w, 511]
        default:return __ldg(facePlane(cb, 0) + (511 - w));                    // back[0, 511-w]
    }
}

__device__ __forceinline__ float load_bot(const float* cb, int f, int w) {
    switch (f) {
        case 0: return __ldg(facePlane(cb, 1) + (size_t)511 * W_ + (511 - w)); // down[511, 511-w]
        case 1: return __ldg(facePlane(cb, 0) + (size_t)511 * W_ + (511 - w)); // back[511, 511-w]
        case 2: return __ldg(facePlane(cb, 1) + w);                            // down[0, w]
        case 3: return __ldg(facePlane(cb, 1) + (size_t)(511 - w) * W_);       // down[511-w, 0]
        case 4: return __ldg(facePlane(cb, 1) + (size_t)w * W_ + 511);         // down[w, 511]
        default:return __ldg(facePlane(cb, 2) + w);                            // front[0, w]
    }
}

__device__ __forceinline__ float load_left(const float* cb, int f, int h) {
    switch (f) {
        case 0: return __ldg(facePlane(cb, 4) + (size_t)h * W_ + 511);           // right[h, 511]
        case 1: return __ldg(facePlane(cb, 3) + (size_t)511 * W_ + (511 - h));   // left[511, 511-h]
        case 2: return __ldg(facePlane(cb, 3) + (size_t)h * W_ + 511);           // left[h, 511]
        case 3: return __ldg(facePlane(cb, 0) + (size_t)h * W_ + 511);           // back[h, 511]
        case 4: return __ldg(facePlane(cb, 2) + (size_t)h * W_ + 511);           // front[h, 511]
        default:return __ldg(facePlane(cb, 3) + h);                              // left[0, h]
    }
}

__device__ __forceinline__ float load_right(const float* cb, int f, int h) {
    switch (f) {
        case 0: return __ldg(facePlane(cb, 3) + (size_t)h * W_);               // left[h, 0]
        case 1: return __ldg(facePlane(cb, 4) + (size_t)511 * W_ + h);         // right[511, h]
        case 2: return __ldg(facePlane(cb, 4) + (size_t)h * W_);               // right[h, 0]
        case 3: return __ldg(facePlane(cb, 2) + (size_t)h * W_);               // front[h, 0]
        case 4: return __ldg(facePlane(cb, 0) + (size_t)h * W_);               // back[h, 0]
        default:return __ldg(facePlane(cb, 4) + (511 - h));                    // right[0, 511-h]
    }
}

// Grid: (1, 514, 768). blockDim = 256. Each block writes one full output row
// (257 float2, 8B-aligned). Interior rows: aligned float2 loads + shfl shift.
__global__ void __launch_bounds__(256)
cubepad_kernel(const float* __restrict__ in, float* __restrict__ out) {
    const int pz = blockIdx.z;        // f*128 + c
    const int y  = blockIdx.y;        // 0..513
    const int f  = pz >> 7;
    const int c  = pz & 127;
    const int j  = threadIdx.x;       // float2 index within output row (0..255)

    float2* __restrict__ orow =
        reinterpret_cast<float2*>(out + ((size_t)pz * OH_ + y) * OW_);

    const float* __restrict__ plane = in + (size_t)pz * ((size_t)H_ * W_);
    const float* __restrict__ cb    = in + (size_t)c  * ((size_t)H_ * W_);

    if (y >= 1 && y <= H_) {
        const int h = y - 1;
        const float* __restrict__ irow = plane + (size_t)h * W_;

        // Aligned, fully-coalesced vector load: v = (in[2j], in[2j+1])
        float2 v = __ldcs(reinterpret_cast<const float2*>(irow) + j);

        // out[2j] = in[2j-1] = prev lane's v.y ; out[2j+1] = in[2j] = v.x
        float left = __shfl_up_sync(0xffffffffu, v.y, 1);
        if ((j & 31) == 0) {
            left = (j == 0) ? load_left(cb, f, h) : __ldg(irow + (2 * j - 1));
        }
        __stcs(orow + j, make_float2(left, v.x));

        if (j == 255) {
            // out[512] = in[511] = v.y ; out[513] = right border
            __stcs(orow + 256, make_float2(v.y, load_right(cb, f, h)));
        }
    } else {
        // top (y==0) or bottom (y==513) row; corners replicate strip endpoints
        const bool top = (y == 0);
        #pragma unroll
        for (int pass = 0; pass < 2; ++pass) {
            int jj = (pass == 0) ? j : 256;
            if (pass == 1 && j != 0) break;
            int x0 = 2 * jj, x1 = 2 * jj + 1;
            int w0 = x0 - 1; w0 = w0 < 0 ? 0 : (w0 > 511 ? 511 : w0);
            int w1 = x1 - 1; w1 = w1 > 511 ? 511 : w1;   // x1 >= 1 always
            float2 v;
            if (top) { v.x = load_top(cb, f, w0); v.y = load_top(cb, f, w1); }
            else     { v.x = load_bot(cb, f, w0); v.y = load_bot(cb, f, w1); }
            __stcs(orow + jj, v);
        }
    }
}

extern "C" void kernel_launch(void* const* d_in, const int* in_sizes, int n_in,
                              void* d_out, int out_size) {
    const float* x = (const float*)d_in[0];
    float* out = (float*)d_out;
    (void)in_sizes; (void)n_in; (void)out_size;  // shapes fixed by problem; pad = 1

    dim3 grid(1, OH_, 6 * C_);
    dim3 block(256);
    cubepad_kernel<<<grid, block>>>(x, out);
}